// round 12
// baseline (speedup 1.0000x reference)
#include <cuda_runtime.h>
#include <math.h>

#define NBLK 740          // 5 CTAs x 148 SMs = one wave
#define TPB  128
#define NWARP (NBLK * 4)

// Per-block partials, entry-major for coalesced reduction.
__device__ float g_part_T[55][NBLK];

__device__ __forceinline__ constexpr int tri_idx(int i, int j) {
    return i * 10 - (i * (i + 1)) / 2 + j;   // i <= j
}

// ---------------------------------------------------------------------------
// Kernel 1: Gram partial reduction, warp-cooperative smem staging (R9 proven),
// readback split into 2-row halves to cut live registers -> 5 CTAs/SM.
// ---------------------------------------------------------------------------
__global__ __launch_bounds__(TPB, 5) void gram_kernel(const float* __restrict__ x,
                                                      int units, int nrows)
{
    __shared__ float4 buf[4][320];          // 5120B per warp
    const float4* __restrict__ xv = (const float4*)x;

    float acc[55];
#pragma unroll
    for (int k = 0; k < 55; k++) acc[k] = 0.f;

    int warp = threadIdx.x >> 5, lane = threadIdx.x & 31;
    int gw = blockIdx.x * 4 + warp;
    float4* wbuf = buf[warp];

    for (int u = gw; u < units; u += NWARP) {
        const float4* __restrict__ src = xv + (size_t)u * 320;
#pragma unroll
        for (int k = 0; k < 10; k++)
            wbuf[lane + 32 * k] = src[lane + 32 * k];
        __syncwarp();
        // First half: lane's rows 0-1 (5 float4 = 20 floats).
        {
            float v[20];
#pragma unroll
            for (int i = 0; i < 5; i++) {
                float4 q = wbuf[10 * lane + i];
                v[4 * i + 0] = q.x; v[4 * i + 1] = q.y;
                v[4 * i + 2] = q.z; v[4 * i + 3] = q.w;
            }
#pragma unroll
            for (int r = 0; r < 2; r++)
#pragma unroll
                for (int i = 0; i < 10; i++)
#pragma unroll
                    for (int j = i; j < 10; j++)
                        acc[tri_idx(i, j)] =
                            fmaf(v[10 * r + i], v[10 * r + j], acc[tri_idx(i, j)]);
        }
        // Second half: lane's rows 2-3.
        {
            float v[20];
#pragma unroll
            for (int i = 0; i < 5; i++) {
                float4 q = wbuf[10 * lane + 5 + i];
                v[4 * i + 0] = q.x; v[4 * i + 1] = q.y;
                v[4 * i + 2] = q.z; v[4 * i + 3] = q.w;
            }
#pragma unroll
            for (int r = 0; r < 2; r++)
#pragma unroll
                for (int i = 0; i < 10; i++)
#pragma unroll
                    for (int j = i; j < 10; j++)
                        acc[tri_idx(i, j)] =
                            fmaf(v[10 * r + i], v[10 * r + j], acc[tri_idx(i, j)]);
        }
        __syncwarp();
    }

    // Deterministic warp shuffle tree reduce per entry.
#pragma unroll
    for (int k = 0; k < 55; k++) {
#pragma unroll
        for (int off = 16; off > 0; off >>= 1)
            acc[k] += __shfl_down_sync(0xffffffffu, acc[k], off);
    }
    __shared__ float red[TPB / 32][55];
    if (lane == 0) {
#pragma unroll
        for (int k = 0; k < 55; k++) red[warp][k] = acc[k];
    }
    __syncthreads();
    if (threadIdx.x < 55) {
        float s = 0.f;
#pragma unroll
        for (int w = 0; w < TPB / 32; w++) s += red[w][threadIdx.x];
        g_part_T[threadIdx.x][blockIdx.x] = s;
    }
}

// ---------------------------------------------------------------------------
// Fast approx primitives (MUFU; <=2^-23 rel err).
// ---------------------------------------------------------------------------
__device__ __forceinline__ float frcp_(float x) {
    float r; asm("rcp.approx.ftz.f32 %0, %1;" : "=f"(r) : "f"(x)); return r;
}
__device__ __forceinline__ float frsqrt_(float x) {
    float r; asm("rsqrt.approx.ftz.f32 %0, %1;" : "=f"(r) : "f"(x)); return r;
}
__device__ __forceinline__ float fsqrt_(float x) {
    return (x > 0.f) ? x * frsqrt_(x) : 0.f;
}
__device__ __forceinline__ float signf_(float a, float b) {
    return b >= 0.f ? fabsf(a) : -fabsf(a);
}
__device__ __forceinline__ float slapy2_1_(float g) {
    float t = fmaf(g, g, 1.f);
    return t * frsqrt_(t);
}
// Branchless Givens (LAPACK sign convention), rsqrt-based.
__device__ __forceinline__ void slartg_(float f, float g, float* cs, float* sn, float* r) {
    float f2   = fmaf(f, f, g * g);
    float rinv = frsqrt_(f2);
    float d    = f2 * rinv;
    float sgn  = (f >= 0.f) ? 1.f : -1.f;
    float cs0  = fabsf(f) * rinv;
    float sn0  = g * rinv * sgn;
    float r0   = sgn * d;
    bool gz = (g == 0.f), fz = (f == 0.f);
    *cs = gz ? 1.f : (fz ? 0.f                      : cs0);
    *sn = gz ? 0.f : (fz ? ((g >= 0.f) ? 1.f : -1.f): sn0);
    *r  = gz ? f   : (fz ? fabsf(g)                 : r0);
}
__device__ __forceinline__ void slaev2_(float a, float b, float cc,
                        float* rt1, float* rt2, float* cs1o, float* sn1o) {
    float sm = a + cc, df = a - cc;
    float adf = fabsf(df), tb = b + b, ab = fabsf(tb);
    float acmx, acmn;
    if (fabsf(a) > fabsf(cc)) { acmx = a;  acmn = cc; }
    else                      { acmx = cc; acmn = a;  }
    float rt;
    if (adf > ab)      { float t = ab * frcp_(adf); float h = fmaf(t, t, 1.f); rt = adf * (h * frsqrt_(h)); }
    else if (adf < ab) { float t = adf * frcp_(ab); float h = fmaf(t, t, 1.f); rt = ab  * (h * frsqrt_(h)); }
    else               rt = ab * 1.41421356237309515f;
    int sgn1;
    if (sm < 0.f)      { *rt1 = 0.5f * (sm - rt); sgn1 = -1;
                         float ri = frcp_(*rt1);
                         *rt2 = (acmx * ri) * acmn - (b * ri) * b; }
    else if (sm > 0.f) { *rt1 = 0.5f * (sm + rt); sgn1 = 1;
                         float ri = frcp_(*rt1);
                         *rt2 = (acmx * ri) * acmn - (b * ri) * b; }
    else               { *rt1 = 0.5f * rt; *rt2 = -0.5f * rt; sgn1 = 1; }
    float cs; int sgn2;
    if (df >= 0.f) { cs = df + rt; sgn2 = 1; }
    else           { cs = df - rt; sgn2 = -1; }
    float acs = fabsf(cs), c1, s1;
    if (acs > ab) { float ct = -tb * frcp_(cs); s1 = frsqrt_(fmaf(ct, ct, 1.f)); c1 = ct * s1; }
    else {
        if (ab == 0.f) { c1 = 1.f; s1 = 0.f; }
        else { float tn = -cs * frcp_(tb); c1 = frsqrt_(fmaf(tn, tn, 1.f)); s1 = tn * c1; }
    }
    if (sgn1 == sgn2) { float t = c1; c1 = -s1; s1 = t; }
    *cs1o = c1; *sn1o = s1;
}

// Predicated register-array access (1-based index).
__device__ __forceinline__ float rget10(const float (&a)[10], int k1) {
    float v = a[0];
#pragma unroll
    for (int k = 2; k <= 10; k++) if (k1 == k) v = a[k - 1];
    return v;
}
__device__ __forceinline__ void rset10(float (&a)[10], int k1, float v) {
#pragma unroll
    for (int k = 1; k <= 10; k++) if (k1 == k) a[k - 1] = v;
}

// ---------------------------------------------------------------------------
// Kernel 2: reduce (4 warps) + warp-0 eigensolver + MLP.
// NO __launch_bounds__: ptxas keeps the solver fully register-resident.
// ---------------------------------------------------------------------------
__global__ void finish_kernel(const float* __restrict__ W1, const float* __restrict__ b1,
                              const float* __restrict__ W2, const float* __restrict__ b2,
                              float* __restrict__ out)
{
    __shared__ float sh_gram[55];
    __shared__ float A[10][10];
    __shared__ float Zsh[10][10];
    __shared__ float wsh[10];
    __shared__ float sW1[160], sb1[16], sW2[16], sb2[1];

    int warp = threadIdx.x >> 5, lane = threadIdx.x & 31;

    // ---- coalesced deterministic reduce: warp w owns entries w, w+4, ... ----
    for (int e = warp; e < 55; e += 4) {
        double s = 0.0;
        for (int k = lane; k < NBLK; k += 32)
            s += (double)g_part_T[e][k];
#pragma unroll
        for (int off = 16; off > 0; off >>= 1)
            s += __shfl_down_sync(0xffffffffu, s, off);
        if (lane == 0) sh_gram[e] = (float)s;
    }
    // weights preload
    for (int idx = threadIdx.x; idx < 160; idx += TPB) sW1[idx] = W1[idx];
    if (threadIdx.x < 16) { sb1[threadIdx.x] = b1[threadIdx.x]; sW2[threadIdx.x] = W2[threadIdx.x]; }
    if (threadIdx.x == 0) sb2[0] = b2[0];
    __syncthreads();
    if (threadIdx.x < 55) {
        int i = 0, rem = threadIdx.x;
        while (rem >= 10 - i) { rem -= 10 - i; i++; }
        int j = i + rem;
        float fv = sh_gram[threadIdx.x];
        A[i][j] = fv; A[j][i] = fv;
    }
    __syncthreads();

    if (warp != 0) return;
    const unsigned M = 0x3ffu;
    if (lane >= 10) return;

    // =======================================================================
    // ssytd2 (UPLO='L'), lane-parallel; approx div/sqrt.
    // =======================================================================
    float dreg[10], ereg[10], taul[9];
#pragma unroll
    for (int ii = 0; ii < 9; ii++) {
        __syncwarp(M);
        float alpha = A[ii + 1][ii];
        float xn2 = 0.f;
#pragma unroll
        for (int r2 = ii + 2; r2 < 10; r2++) xn2 += A[r2][ii] * A[r2][ii];
        float xnorm = fsqrt_(xn2);
        float taui;
        if (xnorm == 0.f) {
            taui = 0.f;
            ereg[ii] = alpha;
        } else {
            float h2 = fmaf(alpha, alpha, xn2);
            float beta = -signf_(h2 * frsqrt_(h2), alpha);
            taui = (beta - alpha) * frcp_(beta);
            float sc = frcp_(alpha - beta);
            ereg[ii] = beta;
            __syncwarp(M);
            if (lane >= ii + 2) A[lane][ii] *= sc;
            if (lane == ii + 1) A[ii + 1][ii] = 1.f;
            __syncwarp(M);
            if (lane >= ii + 1) {
                float s = 0.f;
#pragma unroll
                for (int c2 = ii + 1; c2 < 10; c2++) {
                    float av = (lane >= c2) ? A[lane][c2] : A[c2][lane];
                    s += av * A[c2][ii];
                }
                wsh[lane] = taui * s;
            }
            __syncwarp(M);
            float dot = 0.f;
#pragma unroll
            for (int r2 = ii + 1; r2 < 10; r2++) dot += wsh[r2] * A[r2][ii];
            float alw = -0.5f * taui * dot;
            __syncwarp(M);
            if (lane >= ii + 1) wsh[lane] += alw * A[lane][ii];
            __syncwarp(M);
            if (lane >= ii + 1) {
                for (int c2 = ii + 1; c2 <= lane; c2++)
                    A[lane][c2] -= A[lane][ii] * wsh[c2] + wsh[lane] * A[c2][ii];
            }
            __syncwarp(M);
            if (lane == ii + 1) A[ii + 1][ii] = ereg[ii];
        }
        taul[ii] = taui;
    }
    __syncwarp(M);
#pragma unroll
    for (int k = 0; k < 10; k++) dreg[k] = A[k][k];

    // ---- Q = H(1)..H(n-1): lane j owns column j ----
    float qc[10];
#pragma unroll
    for (int r2 = 0; r2 < 10; r2++) qc[r2] = (r2 == lane) ? 1.f : 0.f;
#pragma unroll
    for (int ii = 8; ii >= 0; ii--) {
        float taui = taul[ii];
        if (taui != 0.f) {
            float s = 0.f;
#pragma unroll
            for (int r2 = 0; r2 < 10; r2++) {
                if (r2 == ii + 1)      s += qc[r2];
                else if (r2 >= ii + 2) s += A[r2][ii] * qc[r2];
            }
            s *= taui;
#pragma unroll
            for (int r2 = 0; r2 < 10; r2++) {
                if (r2 == ii + 1)      qc[r2] -= s;
                else if (r2 >= ii + 2) qc[r2] -= A[r2][ii] * s;
            }
        }
    }
#pragma unroll
    for (int r2 = 0; r2 < 10; r2++) Zsh[r2][lane] = qc[r2];
    __syncwarp(M);
    float z[10];
#pragma unroll
    for (int c2 = 0; c2 < 10; c2++) z[c2] = Zsh[lane][c2];

    // =======================================================================
    // ssteqr ('V'): rotations fused into the recurrence, register-resident.
    // =======================================================================
    {
    const float EPS    = 5.9604645e-08f;
    const float EPS2   = EPS * EPS;
    const float SAFMIN = 1.1754944e-38f;
    int n = 10, nmaxit = n * 30, jtot = 0;
    int l1 = 1, l = 0, lsv, lend, lendsv, m;
    float p, g, r, c, s, f, b, rt1, rt2;

L10:
    if (l1 > n) goto L160;
    if (l1 > 1) rset10(ereg, l1 - 1, 0.f);
    if (l1 <= n - 1) {
        int msel = n; bool fnd = false;
#pragma unroll
        for (int mm = 1; mm <= 9; mm++) {
            if (!fnd && mm >= l1) {
                float tst = fabsf(ereg[mm - 1]);
                if (tst == 0.f) { msel = mm; fnd = true; }
                else {
                    float prod = fabsf(dreg[mm - 1]) * fabsf(dreg[mm]);
                    if (tst <= fsqrt_(prod) * EPS) {
                        ereg[mm - 1] = 0.f; msel = mm; fnd = true;
                    }
                }
            }
        }
        m = msel;
    } else m = n;
    l = l1; lsv = l; lend = m; lendsv = lend; l1 = m + 1;
    if (lend == l) goto L10;
    if (fabsf(rget10(dreg, lend)) < fabsf(rget10(dreg, l))) { lend = lsv; l = lendsv; }
    if (lend > l) goto L40; else goto L90;

    // ============ QL iteration ============
L40:
    if (l != lend) {
        int msel = lend; bool fnd = false;
#pragma unroll
        for (int mm = 1; mm <= 9; mm++) {
            if (!fnd && mm >= l && mm <= lend - 1) {
                float tst = ereg[mm - 1] * ereg[mm - 1];
                if (tst <= EPS2 * fabsf(dreg[mm - 1]) * fabsf(dreg[mm]) + SAFMIN) {
                    msel = mm; fnd = true;
                }
            }
        }
        m = msel;
    } else m = lend;
    if (m < lend) rset10(ereg, m, 0.f);
    p = rget10(dreg, l);
    if (m == l) goto L80;
    if (m == l + 1) {
        slaev2_(rget10(dreg, l), rget10(ereg, l), rget10(dreg, l + 1), &rt1, &rt2, &c, &s);
#pragma unroll
        for (int jj = 0; jj < 9; jj++) if (jj == l - 1) {
            float tmp = z[jj + 1];
            z[jj + 1] = c * tmp - s * z[jj];
            z[jj]     = s * tmp + c * z[jj];
        }
        rset10(dreg, l, rt1); rset10(dreg, l + 1, rt2); rset10(ereg, l, 0.f);
        l += 2;
        if (l <= lend) goto L40;
        goto L140;
    }
    if (jtot == nmaxit) goto L140;
    jtot++;
    {
        float el = rget10(ereg, l);
        g = (rget10(dreg, l + 1) - p) * (0.5f * frcp_(el));
        r = slapy2_1_(g);
        g = rget10(dreg, m) - p + el * frcp_(g + signf_(r, g));
    }
    s = 1.f; c = 1.f; p = 0.f;
#pragma unroll
    for (int i = 9; i >= 1; i--) {
        if (i <= m - 1 && i >= l) {
            f = s * ereg[i - 1]; b = c * ereg[i - 1];
            slartg_(g, f, &c, &s, &r);
            if (i != m - 1) ereg[i] = r;
            g = dreg[i] - p;
            r = (dreg[i - 1] - g) * s + 2.f * c * b;
            p = s * r;
            dreg[i] = g + p;
            g = c * r - b;
            // fused slasr 'B' step: (ct, st) = (c, -s)
            float tmp = z[i];
            z[i]     = c * tmp + s * z[i - 1];
            z[i - 1] = -s * tmp + c * z[i - 1];
        }
    }
    rset10(dreg, l, rget10(dreg, l) - p);
    rset10(ereg, l, g);
    goto L40;
L80:
    rset10(dreg, l, p);
    l++;
    if (l <= lend) goto L40;
    goto L140;

    // ============ QR iteration ============
L90:
    if (l != lend) {
        int msel = lend; bool fnd = false;
#pragma unroll
        for (int mm = 10; mm >= 2; mm--) {
            if (!fnd && mm <= l && mm >= lend + 1) {
                float tst = ereg[mm - 2] * ereg[mm - 2];
                if (tst <= EPS2 * fabsf(dreg[mm - 1]) * fabsf(dreg[mm - 2]) + SAFMIN) {
                    msel = mm; fnd = true;
                }
            }
        }
        m = msel;
    } else m = lend;
    if (m > lend) rset10(ereg, m - 1, 0.f);
    p = rget10(dreg, l);
    if (m == l) goto L130;
    if (m == l - 1) {
        slaev2_(rget10(dreg, l - 1), rget10(ereg, l - 1), rget10(dreg, l), &rt1, &rt2, &c, &s);
#pragma unroll
        for (int jj = 0; jj < 9; jj++) if (jj == l - 2) {
            float tmp = z[jj + 1];
            z[jj + 1] = c * tmp - s * z[jj];
            z[jj]     = s * tmp + c * z[jj];
        }
        rset10(dreg, l - 1, rt1); rset10(dreg, l, rt2); rset10(ereg, l - 1, 0.f);
        l -= 2;
        if (l >= lend) goto L90;
        goto L140;
    }
    if (jtot == nmaxit) goto L140;
    jtot++;
    {
        float el = rget10(ereg, l - 1);
        g = (rget10(dreg, l - 1) - p) * (0.5f * frcp_(el));
        r = slapy2_1_(g);
        g = rget10(dreg, m) - p + el * frcp_(g + signf_(r, g));
    }
    s = 1.f; c = 1.f; p = 0.f;
#pragma unroll
    for (int i = 1; i <= 9; i++) {
        if (i >= m && i <= l - 1) {
            f = s * ereg[i - 1]; b = c * ereg[i - 1];
            slartg_(g, f, &c, &s, &r);
            if (i >= 2) { if (i != m) ereg[i - 2] = r; }
            g = dreg[i - 1] - p;
            r = (dreg[i] - g) * s + 2.f * c * b;
            p = s * r;
            dreg[i - 1] = g + p;
            g = c * r - b;
            // fused slasr 'F' step: (ct, st) = (c, s)
            float tmp = z[i];
            z[i]     = c * tmp - s * z[i - 1];
            z[i - 1] = s * tmp + c * z[i - 1];
        }
    }
    rset10(dreg, l, rget10(dreg, l) - p);
    rset10(ereg, l - 1, g);
    goto L90;
L130:
    rset10(dreg, l, p);
    l--;
    if (l >= lend) goto L90;
    goto L140;

L140:
    if (jtot < nmaxit) goto L10;
    goto L160;

L160:
    // LAPACK ascending selection sort with column swaps.
    for (int ii2 = 2; ii2 <= n; ii2++) {
        int i = ii2 - 1, k = i;
        float pp = rget10(dreg, i);
#pragma unroll
        for (int j = 2; j <= 10; j++) {
            if (j >= ii2) {
                float dj = dreg[j - 1];
                if (dj < pp) { k = j; pp = dj; }
            }
        }
        if (k != i) {
            rset10(dreg, k, rget10(dreg, i));
            rset10(dreg, i, pp);
            float zi = 0.f, zk = 0.f;
#pragma unroll
            for (int cidx = 0; cidx < 10; cidx++) {
                if (cidx == i - 1) zi = z[cidx];
                if (cidx == k - 1) zk = z[cidx];
            }
#pragma unroll
            for (int cidx = 0; cidx < 10; cidx++) {
                if (cidx == i - 1) z[cidx] = zk;
                if (cidx == k - 1) z[cidx] = zi;
            }
        }
    }
    }

    // ---- MLP per-lane: lane i computes output row i ------------------------
    {
        float y2 = sb2[0];
#pragma unroll
        for (int h = 0; h < 16; h++) {
            float a1 = sb1[h];
#pragma unroll
            for (int j = 0; j < 10; j++) a1 = fmaf(z[j], sW1[h * 10 + j], a1);
            a1 = fmaxf(a1, 0.f);
            y2 = fmaf(a1, sW2[h], y2);
        }
        out[lane] = 0.5f * (1.f / (1.f + expf(-y2)) + 1.f);
    }
}

extern "C" void kernel_launch(void* const* d_in, const int* in_sizes, int n_in,
                              void* d_out, int out_size)
{
    const float* x  = (const float*)d_in[0];
    const float* W1 = (const float*)d_in[1];
    const float* b1 = (const float*)d_in[2];
    const float* W2 = (const float*)d_in[3];
    const float* b2 = (const float*)d_in[4];
    int nrows = in_sizes[0] / 10;
    int units = nrows / 128;                 // 128-row units per warp
    gram_kernel<<<NBLK, TPB>>>(x, units, nrows);
    finish_kernel<<<1, TPB>>>(W1, b1, W2, b2, (float*)d_out);
}

// round 13
// speedup vs baseline: 1.2772x; 1.2772x over previous
#include <cuda_runtime.h>
#include <math.h>

#define NBLK 740          // 5 CTAs x 148 SMs = one wave
#define TPB  128
#define NWARP (NBLK * 4)

// Per-block partials, entry-major for coalesced reduction.
__device__ float g_part_T[55][NBLK];
__device__ float g_gram[55];

__device__ __forceinline__ constexpr int tri_idx(int i, int j) {
    return i * 10 - (i * (i + 1)) / 2 + j;   // i <= j
}

// ---------------------------------------------------------------------------
// Kernel 1: Gram partial reduction (R12 version — measured ~27us).
// Warp-cooperative smem staging; readback in 2-row halves -> 5 CTAs/SM.
// ---------------------------------------------------------------------------
__global__ __launch_bounds__(TPB, 5) void gram_kernel(const float* __restrict__ x,
                                                      int units, int nrows)
{
    __shared__ float4 buf[4][320];          // 5120B per warp
    const float4* __restrict__ xv = (const float4*)x;

    float acc[55];
#pragma unroll
    for (int k = 0; k < 55; k++) acc[k] = 0.f;

    int warp = threadIdx.x >> 5, lane = threadIdx.x & 31;
    int gw = blockIdx.x * 4 + warp;
    float4* wbuf = buf[warp];

    for (int u = gw; u < units; u += NWARP) {
        const float4* __restrict__ src = xv + (size_t)u * 320;
#pragma unroll
        for (int k = 0; k < 10; k++)
            wbuf[lane + 32 * k] = src[lane + 32 * k];
        __syncwarp();
        {   // rows 0-1 of this lane
            float v[20];
#pragma unroll
            for (int i = 0; i < 5; i++) {
                float4 q = wbuf[10 * lane + i];
                v[4 * i + 0] = q.x; v[4 * i + 1] = q.y;
                v[4 * i + 2] = q.z; v[4 * i + 3] = q.w;
            }
#pragma unroll
            for (int r = 0; r < 2; r++)
#pragma unroll
                for (int i = 0; i < 10; i++)
#pragma unroll
                    for (int j = i; j < 10; j++)
                        acc[tri_idx(i, j)] =
                            fmaf(v[10 * r + i], v[10 * r + j], acc[tri_idx(i, j)]);
        }
        {   // rows 2-3 of this lane
            float v[20];
#pragma unroll
            for (int i = 0; i < 5; i++) {
                float4 q = wbuf[10 * lane + 5 + i];
                v[4 * i + 0] = q.x; v[4 * i + 1] = q.y;
                v[4 * i + 2] = q.z; v[4 * i + 3] = q.w;
            }
#pragma unroll
            for (int r = 0; r < 2; r++)
#pragma unroll
                for (int i = 0; i < 10; i++)
#pragma unroll
                    for (int j = i; j < 10; j++)
                        acc[tri_idx(i, j)] =
                            fmaf(v[10 * r + i], v[10 * r + j], acc[tri_idx(i, j)]);
        }
        __syncwarp();
    }

    // Deterministic warp shuffle tree reduce per entry.
#pragma unroll
    for (int k = 0; k < 55; k++) {
#pragma unroll
        for (int off = 16; off > 0; off >>= 1)
            acc[k] += __shfl_down_sync(0xffffffffu, acc[k], off);
    }
    __shared__ float red[TPB / 32][55];
    if (lane == 0) {
#pragma unroll
        for (int k = 0; k < 55; k++) red[warp][k] = acc[k];
    }
    __syncthreads();
    if (threadIdx.x < 55) {
        float s = 0.f;
#pragma unroll
        for (int w = 0; w < TPB / 32; w++) s += red[w][threadIdx.x];
        g_part_T[threadIdx.x][blockIdx.x] = s;
    }
}

// ---------------------------------------------------------------------------
// Kernel 2: per-entry coalesced deterministic reduction (R9 version).
// ---------------------------------------------------------------------------
__global__ __launch_bounds__(256, 1) void reduce_kernel()
{
    __shared__ double sh[256];
    int e = blockIdx.x, q = threadIdx.x;
    double s = 0.0;
    for (int k = q; k < NBLK; k += 256)
        s += (double)g_part_T[e][k];
    sh[q] = s;
    __syncthreads();
#pragma unroll
    for (int off = 128; off > 0; off >>= 1) {
        if (q < off) sh[q] += sh[q + off];
        __syncthreads();
    }
    if (q == 0) g_gram[e] = (float)sh[0];
}

// ---------------------------------------------------------------------------
// Fast approx primitives (MUFU; <=2^-23 rel err).
// ---------------------------------------------------------------------------
__device__ __forceinline__ float frcp_(float x) {
    float r; asm("rcp.approx.ftz.f32 %0, %1;" : "=f"(r) : "f"(x)); return r;
}
__device__ __forceinline__ float frsqrt_(float x) {
    float r; asm("rsqrt.approx.ftz.f32 %0, %1;" : "=f"(r) : "f"(x)); return r;
}
__device__ __forceinline__ float fsqrt_(float x) {
    return (x > 0.f) ? x * frsqrt_(x) : 0.f;
}
__device__ __forceinline__ float signf_(float a, float b) {
    return b >= 0.f ? fabsf(a) : -fabsf(a);
}
__device__ __forceinline__ float slapy2_1_(float g) {
    float t = fmaf(g, g, 1.f);
    return t * frsqrt_(t);
}
// Branchless Givens (LAPACK sign convention), rsqrt-based.
__device__ __forceinline__ void slartg_(float f, float g, float* cs, float* sn, float* r) {
    float f2   = fmaf(f, f, g * g);
    float rinv = frsqrt_(f2);
    float d    = f2 * rinv;
    float sgn  = (f >= 0.f) ? 1.f : -1.f;
    float cs0  = fabsf(f) * rinv;
    float sn0  = g * rinv * sgn;
    float r0   = sgn * d;
    bool gz = (g == 0.f), fz = (f == 0.f);
    *cs = gz ? 1.f : (fz ? 0.f                      : cs0);
    *sn = gz ? 0.f : (fz ? ((g >= 0.f) ? 1.f : -1.f): sn0);
    *r  = gz ? f   : (fz ? fabsf(g)                 : r0);
}
__device__ __forceinline__ void slaev2_(float a, float b, float cc,
                        float* rt1, float* rt2, float* cs1o, float* sn1o) {
    float sm = a + cc, df = a - cc;
    float adf = fabsf(df), tb = b + b, ab = fabsf(tb);
    float acmx, acmn;
    if (fabsf(a) > fabsf(cc)) { acmx = a;  acmn = cc; }
    else                      { acmx = cc; acmn = a;  }
    float rt;
    if (adf > ab)      { float t = ab * frcp_(adf); float h = fmaf(t, t, 1.f); rt = adf * (h * frsqrt_(h)); }
    else if (adf < ab) { float t = adf * frcp_(ab); float h = fmaf(t, t, 1.f); rt = ab  * (h * frsqrt_(h)); }
    else               rt = ab * 1.41421356237309515f;
    int sgn1;
    if (sm < 0.f)      { *rt1 = 0.5f * (sm - rt); sgn1 = -1;
                         float ri = frcp_(*rt1);
                         *rt2 = (acmx * ri) * acmn - (b * ri) * b; }
    else if (sm > 0.f) { *rt1 = 0.5f * (sm + rt); sgn1 = 1;
                         float ri = frcp_(*rt1);
                         *rt2 = (acmx * ri) * acmn - (b * ri) * b; }
    else               { *rt1 = 0.5f * rt; *rt2 = -0.5f * rt; sgn1 = 1; }
    float cs; int sgn2;
    if (df >= 0.f) { cs = df + rt; sgn2 = 1; }
    else           { cs = df - rt; sgn2 = -1; }
    float acs = fabsf(cs), c1, s1;
    if (acs > ab) { float ct = -tb * frcp_(cs); s1 = frsqrt_(fmaf(ct, ct, 1.f)); c1 = ct * s1; }
    else {
        if (ab == 0.f) { c1 = 1.f; s1 = 0.f; }
        else { float tn = -cs * frcp_(tb); c1 = frsqrt_(fmaf(tn, tn, 1.f)); s1 = tn * c1; }
    }
    if (sgn1 == sgn2) { float t = c1; c1 = -s1; s1 = t; }
    *cs1o = c1; *sn1o = s1;
}

// Predicated register-array access (1-based index).
__device__ __forceinline__ float rget10(const float (&a)[10], int k1) {
    float v = a[0];
#pragma unroll
    for (int k = 2; k <= 10; k++) if (k1 == k) v = a[k - 1];
    return v;
}
__device__ __forceinline__ void rset10(float (&a)[10], int k1, float v) {
#pragma unroll
    for (int k = 1; k <= 10; k++) if (k1 == k) a[k - 1] = v;
}

// ---------------------------------------------------------------------------
// Kernel 3 (one warp, launch_bounds(32,1) -> full register budget):
// gram -> register-resident eigensolver -> MLP.
// ---------------------------------------------------------------------------
__global__ __launch_bounds__(32, 1)
void finish_kernel(const float* __restrict__ W1, const float* __restrict__ b1,
                   const float* __restrict__ W2, const float* __restrict__ b2,
                   float* __restrict__ out)
{
    __shared__ float A[10][10];
    __shared__ float Zsh[10][10];
    __shared__ float wsh[10];
    __shared__ float sW1[160], sb1[16], sW2[16], sb2[1];

    int lane = threadIdx.x;

    // ---- preload weights + gram (one warp, strided) ----
    for (int idx = lane; idx < 160; idx += 32) sW1[idx] = W1[idx];
    if (lane < 16) { sb1[lane] = b1[lane]; sW2[lane] = W2[lane]; }
    if (lane == 0) sb2[0] = b2[0];
    for (int idx = lane; idx < 55; idx += 32) {
        int i = 0, rem = idx;
        while (rem >= 10 - i) { rem -= 10 - i; i++; }
        int j = i + rem;
        float fv = g_gram[idx];
        A[i][j] = fv; A[j][i] = fv;
    }
    __syncwarp();
    const unsigned M = 0x3ffu;
    if (lane >= 10) return;

    // =======================================================================
    // ssytd2 (UPLO='L'), lane-parallel; approx div/sqrt.
    // =======================================================================
    float dreg[10], ereg[10], taul[9];
#pragma unroll
    for (int ii = 0; ii < 9; ii++) {
        __syncwarp(M);
        float alpha = A[ii + 1][ii];
        float xn2 = 0.f;
#pragma unroll
        for (int r2 = ii + 2; r2 < 10; r2++) xn2 += A[r2][ii] * A[r2][ii];
        float xnorm = fsqrt_(xn2);
        float taui;
        if (xnorm == 0.f) {
            taui = 0.f;
            ereg[ii] = alpha;
        } else {
            float h2 = fmaf(alpha, alpha, xn2);
            float beta = -signf_(h2 * frsqrt_(h2), alpha);
            taui = (beta - alpha) * frcp_(beta);
            float sc = frcp_(alpha - beta);
            ereg[ii] = beta;
            __syncwarp(M);
            if (lane >= ii + 2) A[lane][ii] *= sc;
            if (lane == ii + 1) A[ii + 1][ii] = 1.f;
            __syncwarp(M);
            if (lane >= ii + 1) {
                float s = 0.f;
#pragma unroll
                for (int c2 = ii + 1; c2 < 10; c2++) {
                    float av = (lane >= c2) ? A[lane][c2] : A[c2][lane];
                    s += av * A[c2][ii];
                }
                wsh[lane] = taui * s;
            }
            __syncwarp(M);
            float dot = 0.f;
#pragma unroll
            for (int r2 = ii + 1; r2 < 10; r2++) dot += wsh[r2] * A[r2][ii];
            float alw = -0.5f * taui * dot;
            __syncwarp(M);
            if (lane >= ii + 1) wsh[lane] += alw * A[lane][ii];
            __syncwarp(M);
            if (lane >= ii + 1) {
                for (int c2 = ii + 1; c2 <= lane; c2++)
                    A[lane][c2] -= A[lane][ii] * wsh[c2] + wsh[lane] * A[c2][ii];
            }
            __syncwarp(M);
            if (lane == ii + 1) A[ii + 1][ii] = ereg[ii];
        }
        taul[ii] = taui;
    }
    __syncwarp(M);
#pragma unroll
    for (int k = 0; k < 10; k++) dreg[k] = A[k][k];

    // ---- Q = H(1)..H(n-1): lane j owns column j ----
    float qc[10];
#pragma unroll
    for (int r2 = 0; r2 < 10; r2++) qc[r2] = (r2 == lane) ? 1.f : 0.f;
#pragma unroll
    for (int ii = 8; ii >= 0; ii--) {
        float taui = taul[ii];
        if (taui != 0.f) {
            float s = 0.f;
#pragma unroll
            for (int r2 = 0; r2 < 10; r2++) {
                if (r2 == ii + 1)      s += qc[r2];
                else if (r2 >= ii + 2) s += A[r2][ii] * qc[r2];
            }
            s *= taui;
#pragma unroll
            for (int r2 = 0; r2 < 10; r2++) {
                if (r2 == ii + 1)      qc[r2] -= s;
                else if (r2 >= ii + 2) qc[r2] -= A[r2][ii] * s;
            }
        }
    }
#pragma unroll
    for (int r2 = 0; r2 < 10; r2++) Zsh[r2][lane] = qc[r2];
    __syncwarp(M);
    float z[10];
#pragma unroll
    for (int c2 = 0; c2 < 10; c2++) z[c2] = Zsh[lane][c2];

    // =======================================================================
    // ssteqr ('V'): rotations fused into the recurrence, register-resident.
    // =======================================================================
    {
    const float EPS    = 5.9604645e-08f;
    const float EPS2   = EPS * EPS;
    const float SAFMIN = 1.1754944e-38f;
    int n = 10, nmaxit = n * 30, jtot = 0;
    int l1 = 1, l = 0, lsv, lend, lendsv, m;
    float p, g, r, c, s, f, b, rt1, rt2;

L10:
    if (l1 > n) goto L160;
    if (l1 > 1) rset10(ereg, l1 - 1, 0.f);
    if (l1 <= n - 1) {
        int msel = n; bool fnd = false;
#pragma unroll
        for (int mm = 1; mm <= 9; mm++) {
            if (!fnd && mm >= l1) {
                float tst = fabsf(ereg[mm - 1]);
                if (tst == 0.f) { msel = mm; fnd = true; }
                else {
                    float prod = fabsf(dreg[mm - 1]) * fabsf(dreg[mm]);
                    if (tst <= fsqrt_(prod) * EPS) {
                        ereg[mm - 1] = 0.f; msel = mm; fnd = true;
                    }
                }
            }
        }
        m = msel;
    } else m = n;
    l = l1; lsv = l; lend = m; lendsv = lend; l1 = m + 1;
    if (lend == l) goto L10;
    if (fabsf(rget10(dreg, lend)) < fabsf(rget10(dreg, l))) { lend = lsv; l = lendsv; }
    if (lend > l) goto L40; else goto L90;

    // ============ QL iteration ============
L40:
    if (l != lend) {
        int msel = lend; bool fnd = false;
#pragma unroll
        for (int mm = 1; mm <= 9; mm++) {
            if (!fnd && mm >= l && mm <= lend - 1) {
                float tst = ereg[mm - 1] * ereg[mm - 1];
                if (tst <= EPS2 * fabsf(dreg[mm - 1]) * fabsf(dreg[mm]) + SAFMIN) {
                    msel = mm; fnd = true;
                }
            }
        }
        m = msel;
    } else m = lend;
    if (m < lend) rset10(ereg, m, 0.f);
    p = rget10(dreg, l);
    if (m == l) goto L80;
    if (m == l + 1) {
        slaev2_(rget10(dreg, l), rget10(ereg, l), rget10(dreg, l + 1), &rt1, &rt2, &c, &s);
#pragma unroll
        for (int jj = 0; jj < 9; jj++) if (jj == l - 1) {
            float tmp = z[jj + 1];
            z[jj + 1] = c * tmp - s * z[jj];
            z[jj]     = s * tmp + c * z[jj];
        }
        rset10(dreg, l, rt1); rset10(dreg, l + 1, rt2); rset10(ereg, l, 0.f);
        l += 2;
        if (l <= lend) goto L40;
        goto L140;
    }
    if (jtot == nmaxit) goto L140;
    jtot++;
    {
        float el = rget10(ereg, l);
        g = (rget10(dreg, l + 1) - p) * (0.5f * frcp_(el));
        r = slapy2_1_(g);
        g = rget10(dreg, m) - p + el * frcp_(g + signf_(r, g));
    }
    s = 1.f; c = 1.f; p = 0.f;
#pragma unroll
    for (int i = 9; i >= 1; i--) {
        if (i <= m - 1 && i >= l) {
            f = s * ereg[i - 1]; b = c * ereg[i - 1];
            slartg_(g, f, &c, &s, &r);
            if (i != m - 1) ereg[i] = r;
            g = dreg[i] - p;
            r = (dreg[i - 1] - g) * s + 2.f * c * b;
            p = s * r;
            dreg[i] = g + p;
            g = c * r - b;
            // fused slasr 'B' step: (ct, st) = (c, -s)
            float tmp = z[i];
            z[i]     = c * tmp + s * z[i - 1];
            z[i - 1] = -s * tmp + c * z[i - 1];
        }
    }
    rset10(dreg, l, rget10(dreg, l) - p);
    rset10(ereg, l, g);
    goto L40;
L80:
    rset10(dreg, l, p);
    l++;
    if (l <= lend) goto L40;
    goto L140;

    // ============ QR iteration ============
L90:
    if (l != lend) {
        int msel = lend; bool fnd = false;
#pragma unroll
        for (int mm = 10; mm >= 2; mm--) {
            if (!fnd && mm <= l && mm >= lend + 1) {
                float tst = ereg[mm - 2] * ereg[mm - 2];
                if (tst <= EPS2 * fabsf(dreg[mm - 1]) * fabsf(dreg[mm - 2]) + SAFMIN) {
                    msel = mm; fnd = true;
                }
            }
        }
        m = msel;
    } else m = lend;
    if (m > lend) rset10(ereg, m - 1, 0.f);
    p = rget10(dreg, l);
    if (m == l) goto L130;
    if (m == l - 1) {
        slaev2_(rget10(dreg, l - 1), rget10(ereg, l - 1), rget10(dreg, l), &rt1, &rt2, &c, &s);
#pragma unroll
        for (int jj = 0; jj < 9; jj++) if (jj == l - 2) {
            float tmp = z[jj + 1];
            z[jj + 1] = c * tmp - s * z[jj];
            z[jj]     = s * tmp + c * z[jj];
        }
        rset10(dreg, l - 1, rt1); rset10(dreg, l, rt2); rset10(ereg, l - 1, 0.f);
        l -= 2;
        if (l >= lend) goto L90;
        goto L140;
    }
    if (jtot == nmaxit) goto L140;
    jtot++;
    {
        float el = rget10(ereg, l - 1);
        g = (rget10(dreg, l - 1) - p) * (0.5f * frcp_(el));
        r = slapy2_1_(g);
        g = rget10(dreg, m) - p + el * frcp_(g + signf_(r, g));
    }
    s = 1.f; c = 1.f; p = 0.f;
#pragma unroll
    for (int i = 1; i <= 9; i++) {
        if (i >= m && i <= l - 1) {
            f = s * ereg[i - 1]; b = c * ereg[i - 1];
            slartg_(g, f, &c, &s, &r);
            if (i >= 2) { if (i != m) ereg[i - 2] = r; }
            g = dreg[i - 1] - p;
            r = (dreg[i] - g) * s + 2.f * c * b;
            p = s * r;
            dreg[i - 1] = g + p;
            g = c * r - b;
            // fused slasr 'F' step: (ct, st) = (c, s)
            float tmp = z[i];
            z[i]     = c * tmp - s * z[i - 1];
            z[i - 1] = s * tmp + c * z[i - 1];
        }
    }
    rset10(dreg, l, rget10(dreg, l) - p);
    rset10(ereg, l - 1, g);
    goto L90;
L130:
    rset10(dreg, l, p);
    l--;
    if (l >= lend) goto L90;
    goto L140;

L140:
    if (jtot < nmaxit) goto L10;
    goto L160;

L160:
    // LAPACK ascending selection sort with column swaps.
    for (int ii2 = 2; ii2 <= n; ii2++) {
        int i = ii2 - 1, k = i;
        float pp = rget10(dreg, i);
#pragma unroll
        for (int j = 2; j <= 10; j++) {
            if (j >= ii2) {
                float dj = dreg[j - 1];
                if (dj < pp) { k = j; pp = dj; }
            }
        }
        if (k != i) {
            rset10(dreg, k, rget10(dreg, i));
            rset10(dreg, i, pp);
            float zi = 0.f, zk = 0.f;
#pragma unroll
            for (int cidx = 0; cidx < 10; cidx++) {
                if (cidx == i - 1) zi = z[cidx];
                if (cidx == k - 1) zk = z[cidx];
            }
#pragma unroll
            for (int cidx = 0; cidx < 10; cidx++) {
                if (cidx == i - 1) z[cidx] = zk;
                if (cidx == k - 1) z[cidx] = zi;
            }
        }
    }
    }

    // ---- MLP per-lane: lane i computes output row i ------------------------
    {
        float y2 = sb2[0];
#pragma unroll
        for (int h = 0; h < 16; h++) {
            float a1 = sb1[h];
#pragma unroll
            for (int j = 0; j < 10; j++) a1 = fmaf(z[j], sW1[h * 10 + j], a1);
            a1 = fmaxf(a1, 0.f);
            y2 = fmaf(a1, sW2[h], y2);
        }
        out[lane] = 0.5f * (1.f / (1.f + expf(-y2)) + 1.f);
    }
}

extern "C" void kernel_launch(void* const* d_in, const int* in_sizes, int n_in,
                              void* d_out, int out_size)
{
    const float* x  = (const float*)d_in[0];
    const float* W1 = (const float*)d_in[1];
    const float* b1 = (const float*)d_in[2];
    const float* W2 = (const float*)d_in[3];
    const float* b2 = (const float*)d_in[4];
    int nrows = in_sizes[0] / 10;
    int units = nrows / 128;                 // 128-row units per warp
    gram_kernel<<<NBLK, TPB>>>(x, units, nrows);
    reduce_kernel<<<55, 256>>>();
    finish_kernel<<<1, 32>>>(W1, b1, W2, b2, (float*)d_out);
}

// round 14
// speedup vs baseline: 1.8412x; 1.4416x over previous
#include <cuda_runtime.h>
#include <math.h>

#define NBLK 740          // 5 CTAs x 148 SMs = one wave
#define TPB  128
#define NWARP (NBLK * 4)

// Per-block partials, entry-major for coalesced reduction.
__device__ float g_part_T[55][NBLK];
__device__ float g_gram[55];

__device__ __forceinline__ constexpr int tri_idx(int i, int j) {
    return i * 10 - (i * (i + 1)) / 2 + j;   // i <= j
}

// ---------------------------------------------------------------------------
// Kernel 1: Gram partial reduction, warp-cooperative smem staging.
// Fill: stride-32 float4 (conflict-free). Readback: lane l owns rows
// {l, l+32, l+64, l+96}, each as 5 x LDS.64 -> word-stride 10 across lanes
// = conflict-free per 16-lane phase (10*l mod 32 hits 16 distinct banks).
// ---------------------------------------------------------------------------
__global__ __launch_bounds__(TPB, 5) void gram_kernel(const float* __restrict__ x,
                                                      int units, int nrows)
{
    __shared__ float4 buf[4][320];          // 5120B per warp
    const float4* __restrict__ xv = (const float4*)x;

    float acc[55];
#pragma unroll
    for (int k = 0; k < 55; k++) acc[k] = 0.f;

    int warp = threadIdx.x >> 5, lane = threadIdx.x & 31;
    int gw = blockIdx.x * 4 + warp;
    float4* wbuf = buf[warp];
    const float2* wb2 = (const float2*)wbuf;

    for (int u = gw; u < units; u += NWARP) {
        const float4* __restrict__ src = xv + (size_t)u * 320;
#pragma unroll
        for (int k = 0; k < 10; k++)
            wbuf[lane + 32 * k] = src[lane + 32 * k];
        __syncwarp();
#pragma unroll
        for (int rb = 0; rb < 4; rb++) {
            int row = lane + 32 * rb;
            float v[10];
#pragma unroll
            for (int j = 0; j < 5; j++) {
                float2 q = wb2[5 * row + j];
                v[2 * j] = q.x; v[2 * j + 1] = q.y;
            }
#pragma unroll
            for (int i = 0; i < 10; i++)
#pragma unroll
                for (int j = i; j < 10; j++)
                    acc[tri_idx(i, j)] = fmaf(v[i], v[j], acc[tri_idx(i, j)]);
        }
        __syncwarp();
    }

    // Deterministic warp shuffle tree reduce per entry.
#pragma unroll
    for (int k = 0; k < 55; k++) {
#pragma unroll
        for (int off = 16; off > 0; off >>= 1)
            acc[k] += __shfl_down_sync(0xffffffffu, acc[k], off);
    }
    __shared__ float red[TPB / 32][55];
    if (lane == 0) {
#pragma unroll
        for (int k = 0; k < 55; k++) red[warp][k] = acc[k];
    }
    __syncthreads();
    if (threadIdx.x < 55) {
        float s = 0.f;
#pragma unroll
        for (int w = 0; w < TPB / 32; w++) s += red[w][threadIdx.x];
        g_part_T[threadIdx.x][blockIdx.x] = s;
    }
}

// ---------------------------------------------------------------------------
// Kernel 2: per-entry coalesced deterministic reduction.
// ---------------------------------------------------------------------------
__global__ __launch_bounds__(256, 1) void reduce_kernel()
{
    __shared__ double sh[256];
    int e = blockIdx.x, q = threadIdx.x;
    double s = 0.0;
    for (int k = q; k < NBLK; k += 256)
        s += (double)g_part_T[e][k];
    sh[q] = s;
    __syncthreads();
#pragma unroll
    for (int off = 128; off > 0; off >>= 1) {
        if (q < off) sh[q] += sh[q + off];
        __syncthreads();
    }
    if (q == 0) g_gram[e] = (float)sh[0];
}

// ---------------------------------------------------------------------------
// Fast approx primitives (MUFU; <=2^-23 rel err).
// ---------------------------------------------------------------------------
__device__ __forceinline__ float frcp_(float x) {
    float r; asm("rcp.approx.ftz.f32 %0, %1;" : "=f"(r) : "f"(x)); return r;
}
__device__ __forceinline__ float frsqrt_(float x) {
    float r; asm("rsqrt.approx.ftz.f32 %0, %1;" : "=f"(r) : "f"(x)); return r;
}
__device__ __forceinline__ float fsqrt_(float x) {
    return (x > 0.f) ? x * frsqrt_(x) : 0.f;
}
__device__ __forceinline__ float signf_(float a, float b) {
    return b >= 0.f ? fabsf(a) : -fabsf(a);
}
__device__ __forceinline__ float slapy2_1_(float g) {
    float t = fmaf(g, g, 1.f);
    return t * frsqrt_(t);
}
// Branchless Givens (LAPACK sign convention), rsqrt-based.
__device__ __forceinline__ void slartg_(float f, float g, float* cs, float* sn, float* r) {
    float f2   = fmaf(f, f, g * g);
    float rinv = frsqrt_(f2);
    float d    = f2 * rinv;
    float sgn  = (f >= 0.f) ? 1.f : -1.f;
    float cs0  = fabsf(f) * rinv;
    float sn0  = g * rinv * sgn;
    float r0   = sgn * d;
    bool gz = (g == 0.f), fz = (f == 0.f);
    *cs = gz ? 1.f : (fz ? 0.f                      : cs0);
    *sn = gz ? 0.f : (fz ? ((g >= 0.f) ? 1.f : -1.f): sn0);
    *r  = gz ? f   : (fz ? fabsf(g)                 : r0);
}
__device__ __forceinline__ void slaev2_(float a, float b, float cc,
                        float* rt1, float* rt2, float* cs1o, float* sn1o) {
    float sm = a + cc, df = a - cc;
    float adf = fabsf(df), tb = b + b, ab = fabsf(tb);
    float acmx, acmn;
    if (fabsf(a) > fabsf(cc)) { acmx = a;  acmn = cc; }
    else                      { acmx = cc; acmn = a;  }
    float rt;
    if (adf > ab)      { float t = ab * frcp_(adf); float h = fmaf(t, t, 1.f); rt = adf * (h * frsqrt_(h)); }
    else if (adf < ab) { float t = adf * frcp_(ab); float h = fmaf(t, t, 1.f); rt = ab  * (h * frsqrt_(h)); }
    else               rt = ab * 1.41421356237309515f;
    int sgn1;
    if (sm < 0.f)      { *rt1 = 0.5f * (sm - rt); sgn1 = -1;
                         float ri = frcp_(*rt1);
                         *rt2 = (acmx * ri) * acmn - (b * ri) * b; }
    else if (sm > 0.f) { *rt1 = 0.5f * (sm + rt); sgn1 = 1;
                         float ri = frcp_(*rt1);
                         *rt2 = (acmx * ri) * acmn - (b * ri) * b; }
    else               { *rt1 = 0.5f * rt; *rt2 = -0.5f * rt; sgn1 = 1; }
    float cs; int sgn2;
    if (df >= 0.f) { cs = df + rt; sgn2 = 1; }
    else           { cs = df - rt; sgn2 = -1; }
    float acs = fabsf(cs), c1, s1;
    if (acs > ab) { float ct = -tb * frcp_(cs); s1 = frsqrt_(fmaf(ct, ct, 1.f)); c1 = ct * s1; }
    else {
        if (ab == 0.f) { c1 = 1.f; s1 = 0.f; }
        else { float tn = -cs * frcp_(tb); c1 = frsqrt_(fmaf(tn, tn, 1.f)); s1 = tn * c1; }
    }
    if (sgn1 == sgn2) { float t = c1; c1 = -s1; s1 = t; }
    *cs1o = c1; *sn1o = s1;
}

// Predicated register-array access (1-based index).
__device__ __forceinline__ float rget10(const float (&a)[10], int k1) {
    float v = a[0];
#pragma unroll
    for (int k = 2; k <= 10; k++) if (k1 == k) v = a[k - 1];
    return v;
}
__device__ __forceinline__ void rset10(float (&a)[10], int k1, float v) {
#pragma unroll
    for (int k = 1; k <= 10; k++) if (k1 == k) a[k - 1] = v;
}

// ---------------------------------------------------------------------------
// Kernel 3 (one warp, launch_bounds(32,1)): EXACT R9 solver (separate
// rotation arrays + second predicated pass — measured tail 38.7us).
// ---------------------------------------------------------------------------
__global__ __launch_bounds__(32, 1)
void finish_kernel(const float* __restrict__ W1, const float* __restrict__ b1,
                   const float* __restrict__ W2, const float* __restrict__ b2,
                   float* __restrict__ out)
{
    __shared__ float A[10][10];
    __shared__ float Zsh[10][10];
    __shared__ float wsh[10];
    __shared__ float sW1[160], sb1[16], sW2[16], sb2[1];

    int lane = threadIdx.x;

    for (int idx = lane; idx < 160; idx += 32) sW1[idx] = W1[idx];
    if (lane < 16) { sb1[lane] = b1[lane]; sW2[lane] = W2[lane]; }
    if (lane == 0) sb2[0] = b2[0];
    for (int idx = lane; idx < 55; idx += 32) {
        int i = 0, rem = idx;
        while (rem >= 10 - i) { rem -= 10 - i; i++; }
        int j = i + rem;
        float fv = g_gram[idx];
        A[i][j] = fv; A[j][i] = fv;
    }
    __syncwarp();
    const unsigned M = 0x3ffu;
    if (lane >= 10) return;

    // ---- ssytd2 (UPLO='L'), lane-parallel; approx div/sqrt ----
    float dreg[10], ereg[10], wcr[10], wsr[10], taul[9];
#pragma unroll
    for (int ii = 0; ii < 9; ii++) {
        __syncwarp(M);
        float alpha = A[ii + 1][ii];
        float xn2 = 0.f;
#pragma unroll
        for (int r2 = ii + 2; r2 < 10; r2++) xn2 += A[r2][ii] * A[r2][ii];
        float xnorm = fsqrt_(xn2);
        float taui;
        if (xnorm == 0.f) {
            taui = 0.f;
            ereg[ii] = alpha;
        } else {
            float h2 = fmaf(alpha, alpha, xn2);
            float beta = -signf_(h2 * frsqrt_(h2), alpha);
            taui = (beta - alpha) * frcp_(beta);
            float sc = frcp_(alpha - beta);
            ereg[ii] = beta;
            __syncwarp(M);
            if (lane >= ii + 2) A[lane][ii] *= sc;
            if (lane == ii + 1) A[ii + 1][ii] = 1.f;
            __syncwarp(M);
            if (lane >= ii + 1) {
                float s = 0.f;
#pragma unroll
                for (int c2 = ii + 1; c2 < 10; c2++) {
                    float av = (lane >= c2) ? A[lane][c2] : A[c2][lane];
                    s += av * A[c2][ii];
                }
                wsh[lane] = taui * s;
            }
            __syncwarp(M);
            float dot = 0.f;
#pragma unroll
            for (int r2 = ii + 1; r2 < 10; r2++) dot += wsh[r2] * A[r2][ii];
            float alw = -0.5f * taui * dot;
            __syncwarp(M);
            if (lane >= ii + 1) wsh[lane] += alw * A[lane][ii];
            __syncwarp(M);
            if (lane >= ii + 1) {
                for (int c2 = ii + 1; c2 <= lane; c2++)
                    A[lane][c2] -= A[lane][ii] * wsh[c2] + wsh[lane] * A[c2][ii];
            }
            __syncwarp(M);
            if (lane == ii + 1) A[ii + 1][ii] = ereg[ii];
        }
        taul[ii] = taui;
    }
    __syncwarp(M);
#pragma unroll
    for (int k = 0; k < 10; k++) dreg[k] = A[k][k];

    // ---- Q = H(1)..H(n-1): lane j owns column j ----
    float qc[10];
#pragma unroll
    for (int r2 = 0; r2 < 10; r2++) qc[r2] = (r2 == lane) ? 1.f : 0.f;
#pragma unroll
    for (int ii = 8; ii >= 0; ii--) {
        float taui = taul[ii];
        if (taui != 0.f) {
            float s = 0.f;
#pragma unroll
            for (int r2 = 0; r2 < 10; r2++) {
                if (r2 == ii + 1)      s += qc[r2];
                else if (r2 >= ii + 2) s += A[r2][ii] * qc[r2];
            }
            s *= taui;
#pragma unroll
            for (int r2 = 0; r2 < 10; r2++) {
                if (r2 == ii + 1)      qc[r2] -= s;
                else if (r2 >= ii + 2) qc[r2] -= A[r2][ii] * s;
            }
        }
    }
#pragma unroll
    for (int r2 = 0; r2 < 10; r2++) Zsh[r2][lane] = qc[r2];
    __syncwarp(M);
    float z[10];
#pragma unroll
    for (int c2 = 0; c2 < 10; c2++) z[c2] = Zsh[lane][c2];

    // ---- ssteqr ('V'): R9 structure (rotation arrays + separate pass) ----
    {
    const float EPS    = 5.9604645e-08f;
    const float EPS2   = EPS * EPS;
    const float SAFMIN = 1.1754944e-38f;
    int n = 10, nmaxit = n * 30, jtot = 0;
    int l1 = 1, l = 0, lsv, lend, lendsv, m;
    float p, g, r, c, s, f, b, rt1, rt2;

L10:
    if (l1 > n) goto L160;
    if (l1 > 1) rset10(ereg, l1 - 1, 0.f);
    if (l1 <= n - 1) {
        int msel = n; bool fnd = false;
#pragma unroll
        for (int mm = 1; mm <= 9; mm++) {
            if (!fnd && mm >= l1) {
                float tst = fabsf(ereg[mm - 1]);
                if (tst == 0.f) { msel = mm; fnd = true; }
                else {
                    float prod = fabsf(dreg[mm - 1]) * fabsf(dreg[mm]);
                    if (tst <= fsqrt_(prod) * EPS) {
                        ereg[mm - 1] = 0.f; msel = mm; fnd = true;
                    }
                }
            }
        }
        m = msel;
    } else m = n;
    l = l1; lsv = l; lend = m; lendsv = lend; l1 = m + 1;
    if (lend == l) goto L10;
    if (fabsf(rget10(dreg, lend)) < fabsf(rget10(dreg, l))) { lend = lsv; l = lendsv; }
    if (lend > l) goto L40; else goto L90;

    // ============ QL iteration ============
L40:
    if (l != lend) {
        int msel = lend; bool fnd = false;
#pragma unroll
        for (int mm = 1; mm <= 9; mm++) {
            if (!fnd && mm >= l && mm <= lend - 1) {
                float tst = ereg[mm - 1] * ereg[mm - 1];
                if (tst <= EPS2 * fabsf(dreg[mm - 1]) * fabsf(dreg[mm]) + SAFMIN) {
                    msel = mm; fnd = true;
                }
            }
        }
        m = msel;
    } else m = lend;
    if (m < lend) rset10(ereg, m, 0.f);
    p = rget10(dreg, l);
    if (m == l) goto L80;
    if (m == l + 1) {
        slaev2_(rget10(dreg, l), rget10(ereg, l), rget10(dreg, l + 1), &rt1, &rt2, &c, &s);
#pragma unroll
        for (int jj = 0; jj < 9; jj++) if (jj == l - 1) {
            float tmp = z[jj + 1];
            z[jj + 1] = c * tmp - s * z[jj];
            z[jj]     = s * tmp + c * z[jj];
        }
        rset10(dreg, l, rt1); rset10(dreg, l + 1, rt2); rset10(ereg, l, 0.f);
        l += 2;
        if (l <= lend) goto L40;
        goto L140;
    }
    if (jtot == nmaxit) goto L140;
    jtot++;
    {
        float el = rget10(ereg, l);
        g = (rget10(dreg, l + 1) - p) * (0.5f * frcp_(el));
        r = slapy2_1_(g);
        g = rget10(dreg, m) - p + el * frcp_(g + signf_(r, g));
    }
    s = 1.f; c = 1.f; p = 0.f;
#pragma unroll
    for (int i = 9; i >= 1; i--) {
        if (i <= m - 1 && i >= l) {
            f = s * ereg[i - 1]; b = c * ereg[i - 1];
            slartg_(g, f, &c, &s, &r);
            if (i != m - 1) ereg[i] = r;
            g = dreg[i] - p;
            r = (dreg[i - 1] - g) * s + 2.f * c * b;
            p = s * r;
            dreg[i] = g + p;
            g = c * r - b;
            wcr[i - 1] = c; wsr[i - 1] = -s;
        }
    }
#pragma unroll
    for (int jj = 8; jj >= 0; jj--) {
        if (jj >= l - 1 && jj <= m - 2) {
            float ct = wcr[jj], st = wsr[jj];
            float tmp = z[jj + 1];
            z[jj + 1] = ct * tmp - st * z[jj];
            z[jj]     = st * tmp + ct * z[jj];
        }
    }
    rset10(dreg, l, rget10(dreg, l) - p);
    rset10(ereg, l, g);
    goto L40;
L80:
    rset10(dreg, l, p);
    l++;
    if (l <= lend) goto L40;
    goto L140;

    // ============ QR iteration ============
L90:
    if (l != lend) {
        int msel = lend; bool fnd = false;
#pragma unroll
        for (int mm = 10; mm >= 2; mm--) {
            if (!fnd && mm <= l && mm >= lend + 1) {
                float tst = ereg[mm - 2] * ereg[mm - 2];
                if (tst <= EPS2 * fabsf(dreg[mm - 1]) * fabsf(dreg[mm - 2]) + SAFMIN) {
                    msel = mm; fnd = true;
                }
            }
        }
        m = msel;
    } else m = lend;
    if (m > lend) rset10(ereg, m - 1, 0.f);
    p = rget10(dreg, l);
    if (m == l) goto L130;
    if (m == l - 1) {
        slaev2_(rget10(dreg, l - 1), rget10(ereg, l - 1), rget10(dreg, l), &rt1, &rt2, &c, &s);
#pragma unroll
        for (int jj = 0; jj < 9; jj++) if (jj == l - 2) {
            float tmp = z[jj + 1];
            z[jj + 1] = c * tmp - s * z[jj];
            z[jj]     = s * tmp + c * z[jj];
        }
        rset10(dreg, l - 1, rt1); rset10(dreg, l, rt2); rset10(ereg, l - 1, 0.f);
        l -= 2;
        if (l >= lend) goto L90;
        goto L140;
    }
    if (jtot == nmaxit) goto L140;
    jtot++;
    {
        float el = rget10(ereg, l - 1);
        g = (rget10(dreg, l - 1) - p) * (0.5f * frcp_(el));
        r = slapy2_1_(g);
        g = rget10(dreg, m) - p + el * frcp_(g + signf_(r, g));
    }
    s = 1.f; c = 1.f; p = 0.f;
#pragma unroll
    for (int i = 1; i <= 9; i++) {
        if (i >= m && i <= l - 1) {
            f = s * ereg[i - 1]; b = c * ereg[i - 1];
            slartg_(g, f, &c, &s, &r);
            if (i >= 2) { if (i != m) ereg[i - 2] = r; }
            g = dreg[i - 1] - p;
            r = (dreg[i] - g) * s + 2.f * c * b;
            p = s * r;
            dreg[i - 1] = g + p;
            g = c * r - b;
            wcr[i - 1] = c; wsr[i - 1] = s;
        }
    }
#pragma unroll
    for (int jj = 0; jj <= 8; jj++) {
        if (jj >= m - 1 && jj <= l - 2) {
            float ct = wcr[jj], st = wsr[jj];
            float tmp = z[jj + 1];
            z[jj + 1] = ct * tmp - st * z[jj];
            z[jj]     = st * tmp + ct * z[jj];
        }
    }
    rset10(dreg, l, rget10(dreg, l) - p);
    rset10(ereg, l - 1, g);
    goto L90;
L130:
    rset10(dreg, l, p);
    l--;
    if (l >= lend) goto L90;
    goto L140;

L140:
    if (jtot < nmaxit) goto L10;
    goto L160;

L160:
    // LAPACK ascending selection sort with column swaps.
    for (int ii2 = 2; ii2 <= n; ii2++) {
        int i = ii2 - 1, k = i;
        float pp = rget10(dreg, i);
#pragma unroll
        for (int j = 2; j <= 10; j++) {
            if (j >= ii2) {
                float dj = dreg[j - 1];
                if (dj < pp) { k = j; pp = dj; }
            }
        }
        if (k != i) {
            rset10(dreg, k, rget10(dreg, i));
            rset10(dreg, i, pp);
            float zi = 0.f, zk = 0.f;
#pragma unroll
            for (int cidx = 0; cidx < 10; cidx++) {
                if (cidx == i - 1) zi = z[cidx];
                if (cidx == k - 1) zk = z[cidx];
            }
#pragma unroll
            for (int cidx = 0; cidx < 10; cidx++) {
                if (cidx == i - 1) z[cidx] = zk;
                if (cidx == k - 1) z[cidx] = zi;
            }
        }
    }
    }

    // ---- MLP per-lane: lane i computes output row i ------------------------
    {
        float y2 = sb2[0];
#pragma unroll
        for (int h = 0; h < 16; h++) {
            float a1 = sb1[h];
#pragma unroll
            for (int j = 0; j < 10; j++) a1 = fmaf(z[j], sW1[h * 10 + j], a1);
            a1 = fmaxf(a1, 0.f);
            y2 = fmaf(a1, sW2[h], y2);
        }
        out[lane] = 0.5f * (1.f / (1.f + expf(-y2)) + 1.f);
    }
}

extern "C" void kernel_launch(void* const* d_in, const int* in_sizes, int n_in,
                              void* d_out, int out_size)
{
    const float* x  = (const float*)d_in[0];
    const float* W1 = (const float*)d_in[1];
    const float* b1 = (const float*)d_in[2];
    const float* W2 = (const float*)d_in[3];
    const float* b2 = (const float*)d_in[4];
    int nrows = in_sizes[0] / 10;
    int units = nrows / 128;                 // 128-row units per warp
    gram_kernel<<<NBLK, TPB>>>(x, units, nrows);
    reduce_kernel<<<55, 256>>>();
    finish_kernel<<<1, 32>>>(W1, b1, W2, b2, (float*)d_out);
}